// round 3
// baseline (speedup 1.0000x reference)
#include <cuda_runtime.h>

#define N_NODES 100000
#define NE      1000000
#define F       64

// Scratch (allocation-free rule: __device__ globals), 16B-aligned for float4.
__device__ __align__(16) int   g_deg[N_NODES];
__device__ __align__(16) float g_dinv[N_NODES];
__device__ __align__(16) float g_hs [N_NODES * F];  // (X@W) * dinv[row]
__device__ __align__(16) float g_acc[N_NODES * F];  // scatter accumulator
__device__ __align__(16) float g_h2 [N_NODES * F];  // layer-1 output (post-relu)

__global__ void k_init_deg() {
    int i = blockIdx.x * blockDim.x + threadIdx.x;
    if (i < N_NODES) g_deg[i] = 1;  // self-loop
}

__global__ void k_count_deg(const int* __restrict__ dst) {
    int e = blockIdx.x * blockDim.x + threadIdx.x;
    if (e < NE) atomicAdd(&g_deg[dst[e]], 1);
}

__global__ void k_dinv() {
    int i = blockIdx.x * blockDim.x + threadIdx.x;
    if (i < N_NODES) g_dinv[i] = rsqrtf((float)g_deg[i]);
}

// hs[r][c] = dinv[r] * sum_k X[r][k] * W[k][c];  also zeroes g_acc.
// Block: 256 threads, 64 rows. Thread = (trow4 in 0..15) x (tcol in 0..15),
// handles rows trow4*4..+3, cols tcol*4..+3 (4x4 register block).
__global__ void k_gemm_scale(const float* __restrict__ Xext,
                             const float* __restrict__ W, int useH2) {
    __shared__ float4 sW[64 * 16];      // sW[k*16 + c4] = W[k][4c4..4c4+3]
    __shared__ float  sX[64 * 68];      // padded stride 68 (conflict-free)

    const float* X = useH2 ? g_h2 : Xext;
    const int tid = threadIdx.x;
    const int rowBase = blockIdx.x * 64;

    // Load W (4096 floats = 1024 float4, 4 per thread)
#pragma unroll
    for (int i = 0; i < 4; i++)
        sW[tid + i * 256] = ((const float4*)W)[tid + i * 256];

    // Load X tile: 64 rows x 64 cols (1024 float4, 4 per thread)
#pragma unroll
    for (int i = 0; i < 4; i++) {
        int v    = tid + i * 256;      // float4 id, 0..1023
        int row  = v >> 4;             // 16 float4 per row
        int col4 = v & 15;
        int gr   = rowBase + row;
        float4 x4 = make_float4(0.f, 0.f, 0.f, 0.f);
        if (gr < N_NODES) x4 = ((const float4*)(X + (size_t)gr * F))[col4];
        *(float4*)&sX[row * 68 + col4 * 4] = x4;
    }
    __syncthreads();

    const int tcol  = tid & 15;
    const int trow4 = tid >> 4;  // 0..15
    float4 a[4];
#pragma unroll
    for (int j = 0; j < 4; j++) a[j] = make_float4(0.f, 0.f, 0.f, 0.f);

#pragma unroll 16
    for (int k = 0; k < 64; k++) {
        float4 w = sW[k * 16 + tcol];
#pragma unroll
        for (int j = 0; j < 4; j++) {
            float xv = sX[(trow4 * 4 + j) * 68 + k];
            a[j].x += xv * w.x;
            a[j].y += xv * w.y;
            a[j].z += xv * w.z;
            a[j].w += xv * w.w;
        }
    }

    const int gr0 = rowBase + trow4 * 4;
#pragma unroll
    for (int j = 0; j < 4; j++) {
        int r = gr0 + j;
        if (r < N_NODES) {
            float dv = g_dinv[r];
            float4 o = make_float4(a[j].x * dv, a[j].y * dv,
                                   a[j].z * dv, a[j].w * dv);
            ((float4*)(g_hs  + (size_t)r * F))[tcol] = o;
            ((float4*)(g_acc + (size_t)r * F))[tcol] =
                make_float4(0.f, 0.f, 0.f, 0.f);
        }
    }
}

// acc[dst] += hs[src], 16 threads per edge; float4 gather, 4 scalar REDs.
__global__ void k_scatter(const int* __restrict__ src,
                          const int* __restrict__ dst) {
    int idx = blockIdx.x * blockDim.x + threadIdx.x;
    int e = idx >> 4;
    int t = idx & 15;
    if (e >= NE) return;
    int s = src[e];
    int d = dst[e];
    float4 v = ((const float4*)(g_hs + (size_t)s * F))[t];
    float* p = g_acc + (size_t)d * F + t * 4;
    atomicAdd(p + 0, v.x);
    atomicAdd(p + 1, v.y);
    atomicAdd(p + 2, v.z);
    atomicAdd(p + 3, v.w);
}

// out = [relu]( dinv * (acc + hs) + b )
__global__ void k_finalize(const float* __restrict__ bias,
                           float* __restrict__ outExt,
                           int doRelu, int toH2) {
    int i = blockIdx.x * blockDim.x + threadIdx.x;  // float4 index
    if (i >= N_NODES * 16) return;
    int node = i >> 4;
    int c4   = i & 15;
    float dv = g_dinv[node];
    float4 ac = ((const float4*)g_acc)[i];
    float4 hs = ((const float4*)g_hs)[i];
    float4 b  = ((const float4*)bias)[c4];
    float4 o;
    o.x = dv * (ac.x + hs.x) + b.x;
    o.y = dv * (ac.y + hs.y) + b.y;
    o.z = dv * (ac.z + hs.z) + b.z;
    o.w = dv * (ac.w + hs.w) + b.w;
    if (doRelu) {
        o.x = fmaxf(o.x, 0.f); o.y = fmaxf(o.y, 0.f);
        o.z = fmaxf(o.z, 0.f); o.w = fmaxf(o.w, 0.f);
    }
    float* dstp = toH2 ? g_h2 : outExt;
    ((float4*)dstp)[i] = o;
}

extern "C" void kernel_launch(void* const* d_in, const int* in_sizes, int n_in,
                              void* d_out, int out_size) {
    const float* x  = (const float*)d_in[0];
    const int*   ei = (const int*)d_in[1];   // [2, NE] int32 (JAX x64 disabled)
    const float* W1 = (const float*)d_in[2];
    const float* b1 = (const float*)d_in[3];
    const float* W2 = (const float*)d_in[4];
    const float* b2 = (const float*)d_in[5];
    float*       out = (float*)d_out;

    const int* src = ei;
    const int* dst = ei + NE;

    const int T = 256;
    const int gN   = (N_NODES + T - 1) / T;           // 391
    const int gE   = (NE + T - 1) / T;                // 3907
    const int gGem = (N_NODES + 63) / 64;             // 1563
    const int gSc  = (NE * 16 + T - 1) / T;           // 62500
    const int gFin = (N_NODES * 16 + T - 1) / T;      // 6250

    // degree / normalization
    k_init_deg<<<gN, T>>>();
    k_count_deg<<<gE, T>>>(dst);
    k_dinv<<<gN, T>>>();

    // Layer 1
    k_gemm_scale<<<gGem, T>>>(x, W1, 0);
    k_scatter<<<gSc, T>>>(src, dst);
    k_finalize<<<gFin, T>>>(b1, out, /*relu=*/1, /*toH2=*/1);

    // Layer 2
    k_gemm_scale<<<gGem, T>>>(nullptr, W2, 1);
    k_scatter<<<gSc, T>>>(src, dst);
    k_finalize<<<gFin, T>>>(b2, out, /*relu=*/0, /*toH2=*/0);
}

// round 4
// speedup vs baseline: 1.1651x; 1.1651x over previous
#include <cuda_runtime.h>

#define N_NODES 100000
#define NE      1000000
#define F       64

// Scratch (allocation-free rule: __device__ globals), 16B-aligned.
__device__ __align__(16) int   g_cnt[N_NODES];      // in-degree (no self-loop)
__device__ __align__(16) int   g_off[N_NODES + 1];  // CSR offsets
__device__ __align__(16) int   g_cur[N_NODES];      // fill cursors
__device__ __align__(16) int   g_adj[NE];           // src sorted by dst
__device__ __align__(16) float g_dinv[N_NODES];
__device__ __align__(16) float g_hs [N_NODES * F];  // (X@W) * dinv[row]
__device__ __align__(16) float g_h2 [N_NODES * F];  // layer-1 output (post-relu)

__global__ void k_zero_cnt() {
    int i = blockIdx.x * blockDim.x + threadIdx.x;
    if (i < N_NODES) g_cnt[i] = 0;
}

__global__ void k_count(const int* __restrict__ dst) {
    int e = blockIdx.x * blockDim.x + threadIdx.x;
    if (e < NE) atomicAdd(&g_cnt[dst[e]], 1);
}

// Single-block exclusive scan over g_cnt -> g_off (+ cursor copy g_cur).
__global__ void k_scan() {
    __shared__ int ssum[1024];
    const int T = 1024;
    const int C = (N_NODES + T - 1) / T;  // 98
    int t = threadIdx.x;
    int base = t * C;
    int s = 0;
    for (int i = 0; i < C; i++) {
        int idx = base + i;
        if (idx < N_NODES) s += g_cnt[idx];
    }
    ssum[t] = s;
    __syncthreads();
    for (int off = 1; off < T; off <<= 1) {
        int v = (t >= off) ? ssum[t - off] : 0;
        __syncthreads();
        ssum[t] += v;
        __syncthreads();
    }
    int run = ssum[t] - s;  // exclusive prefix of this thread's chunk
    for (int i = 0; i < C; i++) {
        int idx = base + i;
        if (idx < N_NODES) {
            g_off[idx] = run;
            g_cur[idx] = run;
            run += g_cnt[idx];
        }
    }
    if (t == T - 1) g_off[N_NODES] = run;
}

__global__ void k_fill(const int* __restrict__ src,
                       const int* __restrict__ dst) {
    int e = blockIdx.x * blockDim.x + threadIdx.x;
    if (e >= NE) return;
    int d = dst[e];
    int pos = atomicAdd(&g_cur[d], 1);
    g_adj[pos] = src[e];
}

__global__ void k_dinv() {
    int i = blockIdx.x * blockDim.x + threadIdx.x;
    if (i < N_NODES) g_dinv[i] = rsqrtf((float)(g_cnt[i] + 1));
}

// hs[r][c] = dinv[r] * sum_k X[r][k] * W[k][c].
// Block: 256 threads, 64 rows. Thread = (trow4 0..15) x (tcol 0..15),
// handles rows trow4*4..+3, cols tcol*4..+3 (4x4 register block).
__global__ void k_gemm_scale(const float* __restrict__ Xext,
                             const float* __restrict__ W, int useH2) {
    __shared__ float4 sW[64 * 16];      // sW[k*16 + c4] = W[k][4c4..4c4+3]
    __shared__ float  sX[64 * 68];      // padded stride 68 (conflict-free)

    const float* X = useH2 ? g_h2 : Xext;
    const int tid = threadIdx.x;
    const int rowBase = blockIdx.x * 64;

#pragma unroll
    for (int i = 0; i < 4; i++)
        sW[tid + i * 256] = ((const float4*)W)[tid + i * 256];

#pragma unroll
    for (int i = 0; i < 4; i++) {
        int v    = tid + i * 256;
        int row  = v >> 4;
        int col4 = v & 15;
        int gr   = rowBase + row;
        float4 x4 = make_float4(0.f, 0.f, 0.f, 0.f);
        if (gr < N_NODES) x4 = ((const float4*)(X + (size_t)gr * F))[col4];
        *(float4*)&sX[row * 68 + col4 * 4] = x4;
    }
    __syncthreads();

    const int tcol  = tid & 15;
    const int trow4 = tid >> 4;
    float4 a[4];
#pragma unroll
    for (int j = 0; j < 4; j++) a[j] = make_float4(0.f, 0.f, 0.f, 0.f);

#pragma unroll 16
    for (int k = 0; k < 64; k++) {
        float4 w = sW[k * 16 + tcol];
#pragma unroll
        for (int j = 0; j < 4; j++) {
            float xv = sX[(trow4 * 4 + j) * 68 + k];
            a[j].x += xv * w.x;
            a[j].y += xv * w.y;
            a[j].z += xv * w.z;
            a[j].w += xv * w.w;
        }
    }

    const int gr0 = rowBase + trow4 * 4;
#pragma unroll
    for (int j = 0; j < 4; j++) {
        int r = gr0 + j;
        if (r < N_NODES) {
            float dv = g_dinv[r];
            ((float4*)(g_hs + (size_t)r * F))[tcol] =
                make_float4(a[j].x * dv, a[j].y * dv, a[j].z * dv, a[j].w * dv);
        }
    }
}

// One warp per destination node: acc = hs[n] + sum_{src in CSR} hs[src];
// out = [relu]( dinv[n]*acc + b ). Lane l owns cols [2l, 2l+1] (float2).
__global__ void k_gather(const float* __restrict__ bias,
                         float* __restrict__ outExt,
                         int doRelu, int toH2) {
    int gw   = (blockIdx.x * blockDim.x + threadIdx.x) >> 5;  // warp id
    int lane = threadIdx.x & 31;
    if (gw >= N_NODES) return;

    const float2* hs2 = (const float2*)g_hs;
    int beg = g_off[gw];
    int end = g_off[gw + 1];

    float2 acc = hs2[(size_t)gw * 32 + lane];  // self-loop term

    int j = beg;
    // unroll-by-4 with index prefetch for MLP
    for (; j + 4 <= end; j += 4) {
        int s0 = g_adj[j + 0];
        int s1 = g_adj[j + 1];
        int s2 = g_adj[j + 2];
        int s3 = g_adj[j + 3];
        float2 v0 = hs2[(size_t)s0 * 32 + lane];
        float2 v1 = hs2[(size_t)s1 * 32 + lane];
        float2 v2 = hs2[(size_t)s2 * 32 + lane];
        float2 v3 = hs2[(size_t)s3 * 32 + lane];
        acc.x += v0.x + v1.x + v2.x + v3.x;
        acc.y += v0.y + v1.y + v2.y + v3.y;
    }
    for (; j < end; j++) {
        int s = g_adj[j];
        float2 v = hs2[(size_t)s * 32 + lane];
        acc.x += v.x;
        acc.y += v.y;
    }

    float dv = g_dinv[gw];
    float2 b = ((const float2*)bias)[lane];
    float2 o = make_float2(dv * acc.x + b.x, dv * acc.y + b.y);
    if (doRelu) { o.x = fmaxf(o.x, 0.f); o.y = fmaxf(o.y, 0.f); }
    float2* dstp = toH2 ? (float2*)g_h2 : (float2*)outExt;
    dstp[(size_t)gw * 32 + lane] = o;
}

extern "C" void kernel_launch(void* const* d_in, const int* in_sizes, int n_in,
                              void* d_out, int out_size) {
    const float* x  = (const float*)d_in[0];
    const int*   ei = (const int*)d_in[1];   // [2, NE] int32
    const float* W1 = (const float*)d_in[2];
    const float* b1 = (const float*)d_in[3];
    const float* W2 = (const float*)d_in[4];
    const float* b2 = (const float*)d_in[5];
    float*       out = (float*)d_out;

    const int* src = ei;
    const int* dst = ei + NE;

    const int T = 256;
    const int gN   = (N_NODES + T - 1) / T;        // 391
    const int gE   = (NE + T - 1) / T;             // 3907
    const int gGem = (N_NODES + 63) / 64;          // 1563
    const int gGat = (N_NODES * 32 + T - 1) / T;   // 12500 (1 warp/node)

    // CSR build + normalization (shared by both layers)
    k_zero_cnt<<<gN, T>>>();
    k_count<<<gE, T>>>(dst);
    k_scan<<<1, 1024>>>();
    k_fill<<<gE, T>>>(src, dst);
    k_dinv<<<gN, T>>>();

    // Layer 1
    k_gemm_scale<<<gGem, T>>>(x, W1, 0);
    k_gather<<<gGat, T>>>(b1, out, /*relu=*/1, /*toH2=*/1);

    // Layer 2
    k_gemm_scale<<<gGem, T>>>(nullptr, W2, 1);
    k_gather<<<gGat, T>>>(b2, out, /*relu=*/0, /*toH2=*/0);
}

// round 5
// speedup vs baseline: 2.7411x; 2.3526x over previous
#include <cuda_runtime.h>

#define N_NODES 100000
#define NE      1000000
#define F       64
#define NBLK    ((N_NODES + 255) / 256)   // 391 scan blocks

// Scratch (allocation-free rule: __device__ globals), 16B-aligned.
__device__ __align__(16) int   g_cnt[N_NODES];      // in-degree (no self-loop)
__device__ __align__(16) int   g_off[N_NODES + 1];  // CSR offsets
__device__ __align__(16) int   g_cur[N_NODES];      // fill cursors
__device__ __align__(16) int   g_adj[NE];           // src sorted by dst
__device__ __align__(16) int   g_part[NBLK];        // block partial sums
__device__ __align__(16) int   g_poff[NBLK];        // block offsets
__device__ __align__(16) float g_dinv[N_NODES];
__device__ __align__(16) float g_hs [N_NODES * F];  // (X@W) * dinv[row]
__device__ __align__(16) float g_h2 [N_NODES * F];  // layer-1 output (post-relu)

__global__ void k_zero_cnt() {
    int i = blockIdx.x * blockDim.x + threadIdx.x;
    if (i < N_NODES) g_cnt[i] = 0;
}

// 4 edges per thread (int4 loads), NE % 4 == 0.
__global__ void k_count(const int* __restrict__ dst) {
    int i = blockIdx.x * blockDim.x + threadIdx.x;
    if (i < NE / 4) {
        int4 d = ((const int4*)dst)[i];
        atomicAdd(&g_cnt[d.x], 1);
        atomicAdd(&g_cnt[d.y], 1);
        atomicAdd(&g_cnt[d.z], 1);
        atomicAdd(&g_cnt[d.w], 1);
    }
}

// Scan phase 1: per-block sums of 256 counts.
__global__ void k_scan1() {
    __shared__ int sh[256];
    int t = threadIdx.x;
    int i = blockIdx.x * 256 + t;
    sh[t] = (i < N_NODES) ? g_cnt[i] : 0;
    __syncthreads();
    for (int off = 128; off > 0; off >>= 1) {
        if (t < off) sh[t] += sh[t + off];
        __syncthreads();
    }
    if (t == 0) g_part[blockIdx.x] = sh[0];
}

// Scan phase 2: exclusive scan of NBLK partials (single small block).
__global__ void k_scan2() {
    __shared__ int sh[512];
    int t = threadIdx.x;
    int v = (t < NBLK) ? g_part[t] : 0;
    sh[t] = v;
    __syncthreads();
    for (int off = 1; off < 512; off <<= 1) {
        int u = (t >= off) ? sh[t - off] : 0;
        __syncthreads();
        sh[t] += u;
        __syncthreads();
    }
    if (t < NBLK) g_poff[t] = sh[t] - v;
    if (t == 511) g_off[N_NODES] = sh[511];
}

// Scan phase 3: intra-block exclusive scan + base; writes off, cur, dinv.
__global__ void k_scan3() {
    __shared__ int sh[256];
    int t = threadIdx.x;
    int i = blockIdx.x * 256 + t;
    int v = (i < N_NODES) ? g_cnt[i] : 0;
    sh[t] = v;
    __syncthreads();
    for (int off = 1; off < 256; off <<= 1) {
        int u = (t >= off) ? sh[t - off] : 0;
        __syncthreads();
        sh[t] += u;
        __syncthreads();
    }
    if (i < N_NODES) {
        int o = g_poff[blockIdx.x] + sh[t] - v;
        g_off[i]  = o;
        g_cur[i]  = o;
        g_dinv[i] = rsqrtf((float)(v + 1));
    }
}

__global__ void k_fill(const int* __restrict__ src,
                       const int* __restrict__ dst) {
    int e = blockIdx.x * blockDim.x + threadIdx.x;
    if (e >= NE) return;
    int d = dst[e];
    int pos = atomicAdd(&g_cur[d], 1);
    g_adj[pos] = src[e];
}

// hs[r][c] = dinv[r] * sum_k X[r][k] * W[k][c].
__global__ void k_gemm_scale(const float* __restrict__ Xext,
                             const float* __restrict__ W, int useH2) {
    __shared__ float4 sW[64 * 16];
    __shared__ float  sX[64 * 68];

    const float* X = useH2 ? g_h2 : Xext;
    const int tid = threadIdx.x;
    const int rowBase = blockIdx.x * 64;

#pragma unroll
    for (int i = 0; i < 4; i++)
        sW[tid + i * 256] = ((const float4*)W)[tid + i * 256];

#pragma unroll
    for (int i = 0; i < 4; i++) {
        int v    = tid + i * 256;
        int row  = v >> 4;
        int col4 = v & 15;
        int gr   = rowBase + row;
        float4 x4 = make_float4(0.f, 0.f, 0.f, 0.f);
        if (gr < N_NODES) x4 = ((const float4*)(X + (size_t)gr * F))[col4];
        *(float4*)&sX[row * 68 + col4 * 4] = x4;
    }
    __syncthreads();

    const int tcol  = tid & 15;
    const int trow4 = tid >> 4;
    float4 a[4];
#pragma unroll
    for (int j = 0; j < 4; j++) a[j] = make_float4(0.f, 0.f, 0.f, 0.f);

#pragma unroll 16
    for (int k = 0; k < 64; k++) {
        float4 w = sW[k * 16 + tcol];
#pragma unroll
        for (int j = 0; j < 4; j++) {
            float xv = sX[(trow4 * 4 + j) * 68 + k];
            a[j].x += xv * w.x;
            a[j].y += xv * w.y;
            a[j].z += xv * w.z;
            a[j].w += xv * w.w;
        }
    }

    const int gr0 = rowBase + trow4 * 4;
#pragma unroll
    for (int j = 0; j < 4; j++) {
        int r = gr0 + j;
        if (r < N_NODES) {
            float dv = g_dinv[r];
            ((float4*)(g_hs + (size_t)r * F))[tcol] =
                make_float4(a[j].x * dv, a[j].y * dv, a[j].z * dv, a[j].w * dv);
        }
    }
}

// Half-warp (16 lanes) per node; lane owns a float4 (4 cols). Unroll 8.
// acc = hs[n] + sum_{s in CSR[n]} hs[s]; out = [relu](dinv[n]*acc + b).
__global__ void k_gather(const float* __restrict__ bias,
                         float* __restrict__ outExt,
                         int doRelu, int toH2) {
    int gt   = blockIdx.x * blockDim.x + threadIdx.x;
    int node = gt >> 4;
    int lane = gt & 15;
    if (node >= N_NODES) return;

    const float4* hs4 = (const float4*)g_hs;
    int beg = g_off[node];
    int end = g_off[node + 1];

    float4 acc = hs4[(size_t)node * 16 + lane];  // self-loop

    int j = beg;
    for (; j + 8 <= end; j += 8) {
        int s0 = __ldg(&g_adj[j + 0]);
        int s1 = __ldg(&g_adj[j + 1]);
        int s2 = __ldg(&g_adj[j + 2]);
        int s3 = __ldg(&g_adj[j + 3]);
        int s4 = __ldg(&g_adj[j + 4]);
        int s5 = __ldg(&g_adj[j + 5]);
        int s6 = __ldg(&g_adj[j + 6]);
        int s7 = __ldg(&g_adj[j + 7]);
        float4 v0 = hs4[(size_t)s0 * 16 + lane];
        float4 v1 = hs4[(size_t)s1 * 16 + lane];
        float4 v2 = hs4[(size_t)s2 * 16 + lane];
        float4 v3 = hs4[(size_t)s3 * 16 + lane];
        float4 v4 = hs4[(size_t)s4 * 16 + lane];
        float4 v5 = hs4[(size_t)s5 * 16 + lane];
        float4 v6 = hs4[(size_t)s6 * 16 + lane];
        float4 v7 = hs4[(size_t)s7 * 16 + lane];
        acc.x += ((v0.x + v1.x) + (v2.x + v3.x)) + ((v4.x + v5.x) + (v6.x + v7.x));
        acc.y += ((v0.y + v1.y) + (v2.y + v3.y)) + ((v4.y + v5.y) + (v6.y + v7.y));
        acc.z += ((v0.z + v1.z) + (v2.z + v3.z)) + ((v4.z + v5.z) + (v6.z + v7.z));
        acc.w += ((v0.w + v1.w) + (v2.w + v3.w)) + ((v4.w + v5.w) + (v6.w + v7.w));
    }
    for (; j + 2 <= end; j += 2) {
        int s0 = __ldg(&g_adj[j + 0]);
        int s1 = __ldg(&g_adj[j + 1]);
        float4 v0 = hs4[(size_t)s0 * 16 + lane];
        float4 v1 = hs4[(size_t)s1 * 16 + lane];
        acc.x += v0.x + v1.x;
        acc.y += v0.y + v1.y;
        acc.z += v0.z + v1.z;
        acc.w += v0.w + v1.w;
    }
    if (j < end) {
        int s = __ldg(&g_adj[j]);
        float4 v = hs4[(size_t)s * 16 + lane];
        acc.x += v.x; acc.y += v.y; acc.z += v.z; acc.w += v.w;
    }

    float dv = g_dinv[node];
    float4 b = ((const float4*)bias)[lane];
    float4 o = make_float4(dv * acc.x + b.x, dv * acc.y + b.y,
                           dv * acc.z + b.z, dv * acc.w + b.w);
    if (doRelu) {
        o.x = fmaxf(o.x, 0.f); o.y = fmaxf(o.y, 0.f);
        o.z = fmaxf(o.z, 0.f); o.w = fmaxf(o.w, 0.f);
    }
    float4* dstp = toH2 ? (float4*)g_h2 : (float4*)outExt;
    dstp[(size_t)node * 16 + lane] = o;
}

extern "C" void kernel_launch(void* const* d_in, const int* in_sizes, int n_in,
                              void* d_out, int out_size) {
    const float* x  = (const float*)d_in[0];
    const int*   ei = (const int*)d_in[1];   // [2, NE] int32
    const float* W1 = (const float*)d_in[2];
    const float* b1 = (const float*)d_in[3];
    const float* W2 = (const float*)d_in[4];
    const float* b2 = (const float*)d_in[5];
    float*       out = (float*)d_out;

    const int* src = ei;
    const int* dst = ei + NE;

    const int T = 256;
    const int gN   = NBLK;                          // 391
    const int gE   = (NE + T - 1) / T;              // 3907
    const int gE4  = (NE / 4 + T - 1) / T;          // 977
    const int gGem = (N_NODES + 63) / 64;           // 1563
    const int gGat = (N_NODES * 16 + T - 1) / T;    // 6250 (16 thr/node)

    // CSR build + normalization (shared by both layers)
    k_zero_cnt<<<gN, T>>>();
    k_count<<<gE4, T>>>(dst);
    k_scan1<<<gN, T>>>();
    k_scan2<<<1, 512>>>();
    k_scan3<<<gN, T>>>();
    k_fill<<<gE, T>>>(src, dst);

    // Layer 1
    k_gemm_scale<<<gGem, T>>>(x, W1, 0);
    k_gather<<<gGat, T>>>(b1, out, /*relu=*/1, /*toH2=*/1);

    // Layer 2
    k_gemm_scale<<<gGem, T>>>(nullptr, W2, 1);
    k_gather<<<gGat, T>>>(b2, out, /*relu=*/0, /*toH2=*/0);
}